// round 11
// baseline (speedup 1.0000x reference)
#include <cuda_runtime.h>
#include <cuda_fp16.h>

#define TSEQ    1024
#define NB      512
#define RMAX    7
#define NDIRBLK 74
#define NBLK    (2 * NDIRBLK)
#define VOCABP1 50001
#define LOG2E   1.4426950408889634f
#define HSTR    72    // hs16 row stride (halves), padded vs 64

// Precomputed zx table: zw[dir][token][gate] = emb[token] @ W_dir + b_dir
__device__ float g_zw[2][VOCABP1][256];
// final hidden states: [dir][batch][64]
__device__ float g_h[2 * NB * 64];

static __device__ __forceinline__ unsigned long long pk2(float lo, float hi) {
    unsigned long long r;
    asm("mov.b64 %0, {%1,%2};" : "=l"(r) : "f"(lo), "f"(hi));
    return r;
}
static __device__ __forceinline__ void upk2(unsigned long long v, float &lo, float &hi) {
    asm("mov.b64 {%0,%1}, %2;" : "=f"(lo), "=f"(hi) : "l"(v));
}
static __device__ __forceinline__ void ffma2(unsigned long long &d,
                                             unsigned long long a,
                                             unsigned long long b) {
    asm("fma.rn.f32x2 %0, %1, %2, %0;" : "+l"(d) : "l"(a), "l"(b));
}
static __device__ __forceinline__ float tanha(float x) {
    float r; asm("tanh.approx.f32 %0, %1;" : "=f"(r) : "f"(x)); return r;
}
static __device__ __forceinline__ float sigm_t(float x) {
    // sigmoid(x) = 0.5 + 0.5 * tanh(x/2)  -- 1 MUFU + FMAs
    return fmaf(0.5f, tanha(0.5f * x), 0.5f);
}
static __device__ __forceinline__ void hmma16816(float* d,
                                                 unsigned a0, unsigned a1,
                                                 unsigned a2, unsigned a3,
                                                 unsigned b0, unsigned b1) {
    asm volatile(
        "mma.sync.aligned.m16n8k16.row.col.f32.f16.f16.f32 "
        "{%0,%1,%2,%3}, {%4,%5,%6,%7}, {%8,%9}, {%0,%1,%2,%3};\n"
        : "+f"(d[0]), "+f"(d[1]), "+f"(d[2]), "+f"(d[3])
        : "r"(a0), "r"(a1), "r"(a2), "r"(a3), "r"(b0), "r"(b1));
}

// ============================================================================
// Phase 1: zw[dir][v][j] = sum_k emb[v][k] * W_dir[k][j] + b_dir[j]
// 512 threads: j = tid&255, row-half = tid>>8 (32 rows each).
// ============================================================================
extern "C" __global__ void __launch_bounds__(512, 1)
zw_kernel(const float* __restrict__ emb,
          const float* __restrict__ Wf, const float* __restrict__ bf,
          const float* __restrict__ Wb, const float* __restrict__ bb)
{
    __shared__ __align__(16) float ebuf[64][64];
    const int dir  = blockIdx.y;
    const int base = blockIdx.x * 64;
    const int tid  = threadIdx.x;
    const int j    = tid & 255;
    const int half = tid >> 8;
    const float* W  = dir ? Wb : Wf;
    const float* bv = dir ? bb : bf;

    unsigned long long wreg[32];
#pragma unroll
    for (int p = 0; p < 32; p++)
        wreg[p] = pk2(W[(2 * p) * 256 + j], W[(2 * p + 1) * 256 + j]);
    const float bj = bv[j];

#pragma unroll
    for (int i = 0; i < 8; i++) {
        const int lin = i * 512 + tid;
        const int r = lin >> 6, c = lin & 63;
        const int row = base + r;
        ebuf[r][c] = (row < VOCABP1) ? emb[(long long)row * 64 + c] : 0.f;
    }
    __syncthreads();

    float* outp = &g_zw[dir][0][0];
    const int rbeg = half * 32;
#pragma unroll 1
    for (int rr = 0; rr < 32; rr++) {
        const int r = rbeg + rr;
        if (base + r >= VOCABP1) break;
        const ulonglong2* srow = (const ulonglong2*)(&ebuf[r][0]);
        unsigned long long a0 = 0ull, a1 = 0ull;
#pragma unroll
        for (int q = 0; q < 8; q++) {
            const ulonglong2 v0 = srow[2 * q];
            const ulonglong2 v1 = srow[2 * q + 1];
            ffma2(a0, v0.x, wreg[4 * q + 0]);
            ffma2(a1, v0.y, wreg[4 * q + 1]);
            ffma2(a0, v1.x, wreg[4 * q + 2]);
            ffma2(a1, v1.y, wreg[4 * q + 3]);
        }
        float p0, p1, q0, q1;
        upk2(a0, p0, p1);
        upk2(a1, q0, q1);
        outp[(long long)(base + r) * 256 + j] = bj + ((p0 + q0) + (p1 + q1));
    }
}

// ============================================================================
// Phase 2: recurrent h@U via transposed tensor-core MMA:  z^T = U^T @ h^T.
// 148 blocks x 512 threads (16 warps), ONE barrier per step.
// Warp w owns the 16 z-columns { unit 4w+u + 64*gate } as MMA M; N=8 carries
// sequences. A = U^T fp16 permanent in regs; B = h^T fp16 from smem (LDS.32,
// conflict-free). HMMA chain split 2+2 across two accumulator sets. Gate set
// assembled in-warp via 2 shfl.xor(16). Activations: native MUFU tanh.approx.
// Token ring: 4 slots, ALL initialized in the prologue (dead rows zeroed in
// every slot -- slot 3 was the R10 crash: dead rows never get prefetch
// writes, so an uninitialized slot became a wild g_zw index).
// ============================================================================
extern "C" __global__ void __launch_bounds__(512, 1)
lstm_kernel(const void* __restrict__ xraw,
            const float* __restrict__ Uf, const float* __restrict__ Ub)
{
    __shared__ __align__(16) __half hs16[2][8][HSTR];  // fp16 hidden, double buf
    __shared__ int idxs[4][8];                         // token ids, 4-slot ring

    const int tid  = threadIdx.x;
    const int wid  = tid >> 5;
    const int lane = tid & 31;
    const int lq   = lane >> 2;        // 0..7
    const int lr   = lane & 3;         // 0..3
    const int g0   = lq >> 2;          // 0..1 : my "gate parity"

    const int dir   = (blockIdx.x >= NDIRBLK) ? 1 : 0;
    const int bslot = blockIdx.x - dir * NDIRBLK;
    const int base  = bslot * RMAX;
    const int nrows = min(RMAX, NB - base);

    const int uw     = wid * 4;              // unit group (4 units per warp)
    const int myunit = uw + (lq & 3);
    const int myrow  = 2 * lr + g0;          // stage C row (0..7)
    const int colA   = myunit + 64 * g0;     // z-col for c0/c1; +128 for c2/c3

    const int*       x32 = (const int*)xraw;
    const long long* x64 = (const long long*)xraw;
    const bool is64 = ((x32[1] | x32[3] | x32[5] | x32[7]) == 0);

    const float* U   = dir ? Ub : Uf;
    const float* zwd = &g_zw[dir][0][0];

    // ---- A fragments: U^T fp16, permanent in registers ----
    unsigned afr[4][4];
#pragma unroll
    for (int kt = 0; kt < 4; kt++) {
#pragma unroll
        for (int hh = 0; hh < 2; hh++) {
            const int k0 = kt * 16 + 2 * lr + 8 * hh;
            __half2 lo = __floats2half2_rn(U[k0 * 256 + colA],
                                           U[(k0 + 1) * 256 + colA]);
            __half2 hi = __floats2half2_rn(U[k0 * 256 + colA + 128],
                                           U[(k0 + 1) * 256 + colA + 128]);
            afr[kt][2 * hh]     = *(unsigned*)&lo;   // a0 (hh=0) / a2 (hh=1)
            afr[kt][2 * hh + 1] = *(unsigned*)&hi;   // a1 (hh=0) / a3 (hh=1)
        }
    }

    // ---- prologue: token ids (ALL 4 ring slots), zero both hs buffers ----
    if (tid < 8) {
        if (tid < nrows) {
            const long long xb = (long long)(base + tid) * TSEQ;
#pragma unroll
            for (int q = 0; q < 4; q++) {
                const int tq = dir ? (TSEQ - 1 - q) : q;
                idxs[q][tid] = is64 ? (int)x64[xb + tq] : x32[xb + tq];
            }
        } else {
#pragma unroll
            for (int q = 0; q < 4; q++) idxs[q][tid] = 0;
        }
    }
    {
        unsigned* hz = (unsigned*)&hs16[0][0][0];
        const int nw = (2 * 8 * HSTR * 2) / 4;
        for (int i = tid; i < nw; i += 512) hz[i] = 0u;
    }
    __syncthreads();

    // zx accumulator inits for step 0
    float zc[4];
    {
        const long long tA = idxs[0][2 * lr];
        const long long tB = idxs[0][2 * lr + 1];
        zc[0] = zwd[tA * 256 + colA];
        zc[1] = zwd[tB * 256 + colA];
        zc[2] = zwd[tA * 256 + colA + 128];
        zc[3] = zwd[tB * 256 + colA + 128];
    }
    float hreg = 0.f, creg = 0.f;

#pragma unroll 1
    for (int t = 0; t < TSEQ; t++) {
        const int p = t & 1;

        const int m = idxs[t & 3][myrow];       // my row's mask token

        // prefetch zx for step t+1
        float zn[4];
        {
            const long long tA = idxs[(t + 1) & 3][2 * lr];
            const long long tB = idxs[(t + 1) & 3][2 * lr + 1];
            zn[0] = zwd[tA * 256 + colA];
            zn[1] = zwd[tB * 256 + colA];
            zn[2] = zwd[tA * 256 + colA + 128];
            zn[3] = zwd[tB * 256 + colA + 128];
        }
        // prefetch token id for step t+2 into ring slot (t+2)&3
        if ((tid < nrows) && (t + 2 < TSEQ)) {
            const int tn = dir ? (TSEQ - 1 - (t + 2)) : (t + 2);
            const long long xb = (long long)(base + tid) * TSEQ;
            idxs[(t + 2) & 3][tid] = is64 ? (int)x64[xb + tn] : x32[xb + tn];
        }

        // ========== stage B: z^T = U^T @ h^T + zx (4 HMMA, 2+2 split) ======
        unsigned bf[4][2];
#pragma unroll
        for (int kt = 0; kt < 4; kt++) {
            bf[kt][0] = *(const unsigned*)&hs16[p][lq][kt * 16 + 2 * lr];
            bf[kt][1] = *(const unsigned*)&hs16[p][lq][kt * 16 + 2 * lr + 8];
        }
        float dA[4] = {zc[0], zc[1], zc[2], zc[3]};
        float dB[4] = {0.f, 0.f, 0.f, 0.f};
        hmma16816(dA, afr[0][0], afr[0][1], afr[0][2], afr[0][3], bf[0][0], bf[0][1]);
        hmma16816(dB, afr[2][0], afr[2][1], afr[2][2], afr[2][3], bf[2][0], bf[2][1]);
        hmma16816(dA, afr[1][0], afr[1][1], afr[1][2], afr[1][3], bf[1][0], bf[1][1]);
        hmma16816(dB, afr[3][0], afr[3][1], afr[3][2], afr[3][3], bf[3][0], bf[3][1]);
        float d[4];
#pragma unroll
        for (int i = 0; i < 4; i++) d[i] = dA[i] + dB[i];

        // ========== gate exchange: 2 shfl.xor(16) ==========
        const float sendA = g0 ? d[0] : d[1];
        const float sendB = g0 ? d[2] : d[3];
        const float recvA = __shfl_xor_sync(0xffffffffu, sendA, 16);
        const float recvB = __shfl_xor_sync(0xffffffffu, sendB, 16);
        const float zown0 = g0 ? d[1] : d[0];   // my row, gate g0
        const float zown2 = g0 ? d[3] : d[2];   // my row, gate g0+2
        const float zi = g0 ? recvA : zown0;    // gate 0
        const float zf = g0 ? zown0 : recvA;    // gate 1
        const float zg = g0 ? recvB : zown2;    // gate 2
        const float zo = g0 ? zown2 : recvB;    // gate 3

        // ========== stage C: gates + state update (tanh.approx) ==========
        {
            const float ig = sigm_t(zi);
            const float fg = sigm_t(zf);
            const float gg = tanha(zg);
            const float og = sigm_t(zo);
            const float cn = fmaf(fg, creg, ig * gg);
            const float hn = og * tanha(cn);
            if (m != 0) { creg = cn; hreg = hn; }
            hs16[p ^ 1][myrow][myunit] = __float2half(hreg);
        }

#pragma unroll
        for (int i = 0; i < 4; i++) zc[i] = zn[i];
        __syncthreads();
    }

    if (myrow < nrows)
        g_h[(dir * NB + (base + myrow)) * 64 + myunit] = hreg;
}

// ============================================================================
// Head: out[b] = relu(concat(hf,hb) @ W1 + b1) @ W2 + b2
// ============================================================================
extern "C" __global__ void head_kernel(const float* __restrict__ W1,
                                       const float* __restrict__ b1,
                                       const float* __restrict__ W2,
                                       const float* __restrict__ b2,
                                       float* __restrict__ out)
{
    const int b = blockIdx.x;
    const int u = threadIdx.x;
    const float* hf = &g_h[b * 64];
    const float* hb = &g_h[(NB + b) * 64];
    float acc = b1[u];
#pragma unroll
    for (int k = 0; k < 64; k++) acc = fmaf(hf[k], W1[k * 32 + u], acc);
#pragma unroll
    for (int k = 0; k < 64; k++) acc = fmaf(hb[k], W1[(64 + k) * 32 + u], acc);
    float v = fmaxf(acc, 0.f) * W2[u];
#pragma unroll
    for (int off = 16; off > 0; off >>= 1)
        v += __shfl_xor_sync(0xffffffffu, v, off);
    if (u == 0) out[b] = v + b2[0];
}

extern "C" void kernel_launch(void* const* d_in, const int* in_sizes, int n_in,
                              void* d_out, int out_size)
{
    const void*  x   = d_in[0];
    const float* emb = (const float*)d_in[1];
    const float* Wf  = (const float*)d_in[2];
    const float* Uf  = (const float*)d_in[3];
    const float* bf  = (const float*)d_in[4];
    const float* Wb  = (const float*)d_in[5];
    const float* Ub  = (const float*)d_in[6];
    const float* bb  = (const float*)d_in[7];
    const float* W1  = (const float*)d_in[8];
    const float* b1  = (const float*)d_in[9];
    const float* W2  = (const float*)d_in[10];
    const float* b2  = (const float*)d_in[11];

    zw_kernel<<<dim3((VOCABP1 + 63) / 64, 2), 512>>>(emb, Wf, bf, Wb, bb);
    lstm_kernel<<<NBLK, 512>>>(x, Uf, Ub);
    head_kernel<<<NB, 32>>>(W1, b1, W2, b2, (float*)d_out);
}

// round 12
// speedup vs baseline: 1.3062x; 1.3062x over previous
#include <cuda_runtime.h>
#include <cuda_fp16.h>

#define TSEQ    1024
#define NB      512
#define RMAX    7
#define NDIRBLK 74
#define NBLK    (2 * NDIRBLK)
#define VOCABP1 50001
#define LOG2E   1.4426950408889634f
#define HSTR    72    // hs16 row stride (halves), padded vs 64

// Precomputed zx table: zw[dir][token][gate] = emb[token] @ W_dir + b_dir
__device__ float g_zw[2][VOCABP1][256];
// final hidden states: [dir][batch][64]
__device__ float g_h[2 * NB * 64];

static __device__ __forceinline__ unsigned long long pk2(float lo, float hi) {
    unsigned long long r;
    asm("mov.b64 %0, {%1,%2};" : "=l"(r) : "f"(lo), "f"(hi));
    return r;
}
static __device__ __forceinline__ void upk2(unsigned long long v, float &lo, float &hi) {
    asm("mov.b64 {%0,%1}, %2;" : "=f"(lo), "=f"(hi) : "l"(v));
}
static __device__ __forceinline__ void ffma2(unsigned long long &d,
                                             unsigned long long a,
                                             unsigned long long b) {
    asm("fma.rn.f32x2 %0, %1, %2, %0;" : "+l"(d) : "l"(a), "l"(b));
}
static __device__ __forceinline__ float tanha(float x) {
    float r; asm("tanh.approx.f32 %0, %1;" : "=f"(r) : "f"(x)); return r;
}
static __device__ __forceinline__ float sigm_t(float x) {
    // sigmoid(x) = 0.5 + 0.5 * tanh(x/2)  -- 1 MUFU + FMAs
    return fmaf(0.5f, tanha(0.5f * x), 0.5f);
}
static __device__ __forceinline__ void hmma16816(float* d,
                                                 unsigned a0, unsigned a1,
                                                 unsigned a2, unsigned a3,
                                                 unsigned b0, unsigned b1) {
    asm volatile(
        "mma.sync.aligned.m16n8k16.row.col.f32.f16.f16.f32 "
        "{%0,%1,%2,%3}, {%4,%5,%6,%7}, {%8,%9}, {%0,%1,%2,%3};\n"
        : "+f"(d[0]), "+f"(d[1]), "+f"(d[2]), "+f"(d[3])
        : "r"(a0), "r"(a1), "r"(a2), "r"(a3), "r"(b0), "r"(b1));
}

// ============================================================================
// Phase 1: zw[dir][v][j] = sum_k emb[v][k] * W_dir[k][j] + b_dir[j]
// (256-thread version -- proven 102.8us)
// ============================================================================
extern "C" __global__ void __launch_bounds__(256, 2)
zw_kernel(const float* __restrict__ emb,
          const float* __restrict__ Wf, const float* __restrict__ bf,
          const float* __restrict__ Wb, const float* __restrict__ bb)
{
    __shared__ __align__(16) float ebuf[64][64];
    const int dir  = blockIdx.y;
    const int base = blockIdx.x * 64;
    const int j    = threadIdx.x;
    const float* W  = dir ? Wb : Wf;
    const float* bv = dir ? bb : bf;

    unsigned long long wreg[32];
#pragma unroll
    for (int p = 0; p < 32; p++)
        wreg[p] = pk2(W[(2 * p) * 256 + j], W[(2 * p + 1) * 256 + j]);
    const float bj = bv[j];

#pragma unroll
    for (int i = 0; i < 16; i++) {
        const int lin = i * 256 + j;
        const int r = lin >> 6, c = lin & 63;
        const int row = base + r;
        ebuf[r][c] = (row < VOCABP1) ? emb[(long long)row * 64 + c] : 0.f;
    }
    __syncthreads();

    float* outp = &g_zw[dir][0][0];
#pragma unroll 1
    for (int r = 0; r < 64; r++) {
        if (base + r >= VOCABP1) break;
        const ulonglong2* srow = (const ulonglong2*)(&ebuf[r][0]);
        unsigned long long a0 = 0ull, a1 = 0ull;
#pragma unroll
        for (int q = 0; q < 8; q++) {
            const ulonglong2 v0 = srow[2 * q];
            const ulonglong2 v1 = srow[2 * q + 1];
            ffma2(a0, v0.x, wreg[4 * q + 0]);
            ffma2(a1, v0.y, wreg[4 * q + 1]);
            ffma2(a0, v1.x, wreg[4 * q + 2]);
            ffma2(a1, v1.y, wreg[4 * q + 3]);
        }
        float p0, p1, q0, q1;
        upk2(a0, p0, p1);
        upk2(a1, q0, q1);
        outp[(long long)(base + r) * 256 + j] = bj + ((p0 + q0) + (p1 + q1));
    }
}

// ============================================================================
// Phase 2: recurrent h@U via transposed tensor-core MMA:  z^T = U^T @ h^T.
// 148 blocks x 512 threads (16 warps), ONE barrier per step.
// DEPTH-2 zx prefetch: at step t the LDGs for step t+2's zx are issued (2 full
// steps of slack -> covers DRAM-tier latency on the 102MB g_zw table, which
// one-step lookahead did not). Token ring: 8 slots; token for step t+4 is
// written at step t (slots t, t+2, t+4 are distinct mod 8; every read/write
// pair is >=2 barriers apart). Dead rows: all 8 slots zeroed in the prologue.
// ============================================================================
extern "C" __global__ void __launch_bounds__(512, 1)
lstm_kernel(const void* __restrict__ xraw,
            const float* __restrict__ Uf, const float* __restrict__ Ub)
{
    __shared__ __align__(16) __half hs16[2][8][HSTR];  // fp16 hidden, double buf
    __shared__ int idxs[8][8];                         // token ids, 8-slot ring

    const int tid  = threadIdx.x;
    const int wid  = tid >> 5;
    const int lane = tid & 31;
    const int lq   = lane >> 2;        // 0..7
    const int lr   = lane & 3;         // 0..3
    const int g0   = lq >> 2;          // 0..1 : my "gate parity"

    const int dir   = (blockIdx.x >= NDIRBLK) ? 1 : 0;
    const int bslot = blockIdx.x - dir * NDIRBLK;
    const int base  = bslot * RMAX;
    const int nrows = min(RMAX, NB - base);

    const int uw     = wid * 4;              // unit group (4 units per warp)
    const int myunit = uw + (lq & 3);
    const int myrow  = 2 * lr + g0;          // stage C row (0..7)
    const int colA   = myunit + 64 * g0;     // z-col for c0/c1; +128 for c2/c3

    const int*       x32 = (const int*)xraw;
    const long long* x64 = (const long long*)xraw;
    const bool is64 = ((x32[1] | x32[3] | x32[5] | x32[7]) == 0);

    const float* U   = dir ? Ub : Uf;
    const float* zwd = &g_zw[dir][0][0];

    // ---- A fragments: U^T fp16, permanent in registers ----
    unsigned afr[4][4];
#pragma unroll
    for (int kt = 0; kt < 4; kt++) {
#pragma unroll
        for (int hh = 0; hh < 2; hh++) {
            const int k0 = kt * 16 + 2 * lr + 8 * hh;
            __half2 lo = __floats2half2_rn(U[k0 * 256 + colA],
                                           U[(k0 + 1) * 256 + colA]);
            __half2 hi = __floats2half2_rn(U[k0 * 256 + colA + 128],
                                           U[(k0 + 1) * 256 + colA + 128]);
            afr[kt][2 * hh]     = *(unsigned*)&lo;   // a0 (hh=0) / a2 (hh=1)
            afr[kt][2 * hh + 1] = *(unsigned*)&hi;   // a1 (hh=0) / a3 (hh=1)
        }
    }

    // ---- prologue ----
    // Dead rows: zero ALL 8 ring slots (they never get prefetch writes).
    // Live rows: slots 0..3 = tokens for steps 0..3 (slot s for s>=4 is
    // written at step s-4 before any reader).
    if (tid < 8) {
        if (tid < nrows) {
            const long long xb = (long long)(base + tid) * TSEQ;
#pragma unroll
            for (int q = 0; q < 4; q++) {
                const int tq = dir ? (TSEQ - 1 - q) : q;
                idxs[q][tid] = is64 ? (int)x64[xb + tq] : x32[xb + tq];
            }
        } else {
#pragma unroll
            for (int q = 0; q < 8; q++) idxs[q][tid] = 0;
        }
    }
    {
        unsigned* hz = (unsigned*)&hs16[0][0][0];
        const int nw = (2 * 8 * HSTR * 2) / 4;
        for (int i = tid; i < nw; i += 512) hz[i] = 0u;
    }
    __syncthreads();

    // zx for steps 0 (zc) and 1 (zn)
    float zc[4], zn[4];
    {
        const long long tA0 = idxs[0][2 * lr], tB0 = idxs[0][2 * lr + 1];
        zc[0] = zwd[tA0 * 256 + colA];
        zc[1] = zwd[tB0 * 256 + colA];
        zc[2] = zwd[tA0 * 256 + colA + 128];
        zc[3] = zwd[tB0 * 256 + colA + 128];
        const long long tA1 = idxs[1][2 * lr], tB1 = idxs[1][2 * lr + 1];
        zn[0] = zwd[tA1 * 256 + colA];
        zn[1] = zwd[tB1 * 256 + colA];
        zn[2] = zwd[tA1 * 256 + colA + 128];
        zn[3] = zwd[tB1 * 256 + colA + 128];
    }
    float hreg = 0.f, creg = 0.f;

#pragma unroll 1
    for (int t = 0; t < TSEQ; t++) {
        const int p = t & 1;

        const int m = idxs[t & 7][myrow];       // my row's mask token

        // issue zx prefetch for step t+2 FIRST (2 steps of latency slack)
        float zn2[4] = {0.f, 0.f, 0.f, 0.f};
        if (t + 2 < TSEQ) {
            const long long tA = idxs[(t + 2) & 7][2 * lr];
            const long long tB = idxs[(t + 2) & 7][2 * lr + 1];
            zn2[0] = zwd[tA * 256 + colA];
            zn2[1] = zwd[tB * 256 + colA];
            zn2[2] = zwd[tA * 256 + colA + 128];
            zn2[3] = zwd[tB * 256 + colA + 128];
        }
        // prefetch token id for step t+4 into ring slot (t+4)&7
        if ((tid < nrows) && (t + 4 < TSEQ)) {
            const int tn = dir ? (TSEQ - 1 - (t + 4)) : (t + 4);
            const long long xb = (long long)(base + tid) * TSEQ;
            idxs[(t + 4) & 7][tid] = is64 ? (int)x64[xb + tn] : x32[xb + tn];
        }

        // ========== stage B: z^T = U^T @ h^T + zx (4 HMMA, 2+2 split) ======
        unsigned bf[4][2];
#pragma unroll
        for (int kt = 0; kt < 4; kt++) {
            bf[kt][0] = *(const unsigned*)&hs16[p][lq][kt * 16 + 2 * lr];
            bf[kt][1] = *(const unsigned*)&hs16[p][lq][kt * 16 + 2 * lr + 8];
        }
        float dA[4] = {zc[0], zc[1], zc[2], zc[3]};
        float dB[4] = {0.f, 0.f, 0.f, 0.f};
        hmma16816(dA, afr[0][0], afr[0][1], afr[0][2], afr[0][3], bf[0][0], bf[0][1]);
        hmma16816(dB, afr[2][0], afr[2][1], afr[2][2], afr[2][3], bf[2][0], bf[2][1]);
        hmma16816(dA, afr[1][0], afr[1][1], afr[1][2], afr[1][3], bf[1][0], bf[1][1]);
        hmma16816(dB, afr[3][0], afr[3][1], afr[3][2], afr[3][3], bf[3][0], bf[3][1]);
        float d[4];
#pragma unroll
        for (int i = 0; i < 4; i++) d[i] = dA[i] + dB[i];

        // ========== gate exchange: 2 shfl.xor(16) ==========
        const float sendA = g0 ? d[0] : d[1];
        const float sendB = g0 ? d[2] : d[3];
        const float recvA = __shfl_xor_sync(0xffffffffu, sendA, 16);
        const float recvB = __shfl_xor_sync(0xffffffffu, sendB, 16);
        const float zown0 = g0 ? d[1] : d[0];   // my row, gate g0
        const float zown2 = g0 ? d[3] : d[2];   // my row, gate g0+2
        const float zi = g0 ? recvA : zown0;    // gate 0
        const float zf = g0 ? zown0 : recvA;    // gate 1
        const float zg = g0 ? recvB : zown2;    // gate 2
        const float zo = g0 ? zown2 : recvB;    // gate 3

        // ========== stage C: gates + state update (tanh.approx) ==========
        {
            const float ig = sigm_t(zi);
            const float fg = sigm_t(zf);
            const float gg = tanha(zg);
            const float og = sigm_t(zo);
            const float cn = fmaf(fg, creg, ig * gg);
            const float hn = og * tanha(cn);
            if (m != 0) { creg = cn; hreg = hn; }
            hs16[p ^ 1][myrow][myunit] = __float2half(hreg);
        }

        // rotate the zx ring
#pragma unroll
        for (int i = 0; i < 4; i++) { zc[i] = zn[i]; zn[i] = zn2[i]; }
        __syncthreads();
    }

    if (myrow < nrows)
        g_h[(dir * NB + (base + myrow)) * 64 + myunit] = hreg;
}

// ============================================================================
// Head: out[b] = relu(concat(hf,hb) @ W1 + b1) @ W2 + b2
// ============================================================================
extern "C" __global__ void head_kernel(const float* __restrict__ W1,
                                       const float* __restrict__ b1,
                                       const float* __restrict__ W2,
                                       const float* __restrict__ b2,
                                       float* __restrict__ out)
{
    const int b = blockIdx.x;
    const int u = threadIdx.x;
    const float* hf = &g_h[b * 64];
    const float* hb = &g_h[(NB + b) * 64];
    float acc = b1[u];
#pragma unroll
    for (int k = 0; k < 64; k++) acc = fmaf(hf[k], W1[k * 32 + u], acc);
#pragma unroll
    for (int k = 0; k < 64; k++) acc = fmaf(hb[k], W1[(64 + k) * 32 + u], acc);
    float v = fmaxf(acc, 0.f) * W2[u];
#pragma unroll
    for (int off = 16; off > 0; off >>= 1)
        v += __shfl_xor_sync(0xffffffffu, v, off);
    if (u == 0) out[b] = v + b2[0];
}

extern "C" void kernel_launch(void* const* d_in, const int* in_sizes, int n_in,
                              void* d_out, int out_size)
{
    const void*  x   = d_in[0];
    const float* emb = (const float*)d_in[1];
    const float* Wf  = (const float*)d_in[2];
    const float* Uf  = (const float*)d_in[3];
    const float* bf  = (const float*)d_in[4];
    const float* Wb  = (const float*)d_in[5];
    const float* Ub  = (const float*)d_in[6];
    const float* bb  = (const float*)d_in[7];
    const float* W1  = (const float*)d_in[8];
    const float* b1  = (const float*)d_in[9];
    const float* W2  = (const float*)d_in[10];
    const float* b2  = (const float*)d_in[11];

    zw_kernel<<<dim3((VOCABP1 + 63) / 64, 2), 256>>>(emb, Wf, bf, Wb, bb);
    lstm_kernel<<<NBLK, 512>>>(x, Uf, Ub);
    head_kernel<<<NB, 32>>>(W1, b1, W2, b2, (float*)d_out);
}